// round 13
// baseline (speedup 1.0000x reference)
#include <cuda_runtime.h>
#include <cuda_bf16.h>
#include <math.h>
#include <stdint.h>

// Problem constants
#define NB 16          // batch
#define LQ 300         // queries
#define CC 256         // channels
#define NH 8           // heads
#define HD 32          // head dim
#define NL 3           // levels
#define NP 4           // points
#define LV 8400        // total spatial positions
#define TPX 96         // H*L*P
#define NQ (NB * LQ)   // 4800 flat queries

// Scratch (device globals; no runtime allocation allowed)
__device__ float  g_v[NB * LV * CC];          // value @ W_val + b_val   (137.6 MB)
__device__ float  g_off[NQ * 192];            // offset GEMM out         (3.7 MB)
__device__ float  g_attn[NQ * TPX];           // attn GEMM out (pre-softmax)
__device__ float  g_mid[NQ * CC];             // per-head aggregated     (4.9 MB)

__constant__ int c_start[NL] = {0, 6400, 8000};
__constant__ int c_w[NL]     = {80, 40, 20};
__constant__ int c_h[NL]     = {80, 40, 20};

// ---------------------------------------------------------------------------
// TF32 tensor-core GEMM: C = A(MxK) @ B(KxN) + bias
// BM=128, BN=128 (min column tiles -> min A re-reads), BK=16,
// DOUBLE-BUFFERED smem: one __syncthreads per k-iter; commit of tile i+1
// overlaps MMA of tile i. 256 threads = 8 warps (2M x 4N), warp tile 64x32.
// As pitch 20 -> bank=(20r+k)%32 bijective over 8x4 frag footprint.
// Per-output k-order identical to BK=32 version (bit-stable rel_err).
// K % 16 == 0; M, N guarded.
// ---------------------------------------------------------------------------
__device__ __forceinline__ uint32_t f2tf32(float f) {
    uint32_t r;
    asm("cvt.rna.tf32.f32 %0, %1;" : "=r"(r) : "f"(f));
    return r;
}

__global__ __launch_bounds__(256) void gemm_tf32(
    const float* __restrict__ A, const float* __restrict__ B,
    const float* __restrict__ bias, float* __restrict__ C,
    int M, int N, int K)
{
    __shared__ uint32_t As[2][128][20];   // [buf][m][k]  (2*128*20*4 = 20.5 KB)
    __shared__ uint32_t Bs[2][16][132];   // [buf][k][n]  (2*16*132*4 = 16.9 KB)

    const int tid  = threadIdx.x;
    const int lane = tid & 31;
    const int warp = tid >> 5;
    const int wm = (warp >> 2) * 64;   // warp M offset (0 or 64)
    const int wn = (warp & 3) * 32;    // warp N offset (0,32,64,96)
    const int rowBase = blockIdx.y * 128;
    const int colBase = blockIdx.x * 128;

    float acc[4][4][4];
#pragma unroll
    for (int i = 0; i < 4; i++)
#pragma unroll
        for (int j = 0; j < 4; j++)
#pragma unroll
            for (int r = 0; r < 4; r++) acc[i][j][r] = 0.f;

    // A: 128x16 = 2048 elems = 256 thr * 2 float4.  64 rows per pass.
    const int arow = tid >> 2;          // 0..63
    const int acol = (tid & 3) * 4;     // 0,4,8,12
    // B: 16x128 = 2048 elems = 256 thr * 2 float4.  8 rows per pass.
    const int brow = tid >> 5;          // 0..7
    const int bcol = (tid & 31) * 4;    // 0..124

    const int nIter = K >> 4;           // K/16 tiles

    float4 stA[2], stB[2];

    // Prologue: stage k-tile 0 and commit to buffer 0
#pragma unroll
    for (int p = 0; p < 2; p++) {
        int gr = rowBase + arow + p * 64;
        stA[p] = (gr < M) ? *(const float4*)&A[(size_t)gr * K + acol]
                          : make_float4(0.f, 0.f, 0.f, 0.f);
        int gc = colBase + bcol;
        stB[p] = (gc < N) ? *(const float4*)&B[(size_t)(brow + p * 8) * N + gc]
                          : make_float4(0.f, 0.f, 0.f, 0.f);
    }
#pragma unroll
    for (int p = 0; p < 2; p++) {
        uint4 pa;
        pa.x = f2tf32(stA[p].x); pa.y = f2tf32(stA[p].y);
        pa.z = f2tf32(stA[p].z); pa.w = f2tf32(stA[p].w);
        *(uint4*)&As[0][arow + p * 64][acol] = pa;
        uint4 pb;
        pb.x = f2tf32(stB[p].x); pb.y = f2tf32(stB[p].y);
        pb.z = f2tf32(stB[p].z); pb.w = f2tf32(stB[p].w);
        *(uint4*)&Bs[0][brow + p * 8][bcol] = pb;
    }
    __syncthreads();

    for (int it = 0; it < nIter; it++) {
        const int cur = it & 1;
        const int nxt = cur ^ 1;
        const bool more = (it + 1) < nIter;

        // Prefetch tile it+1 into registers (global latency overlaps MMA)
        if (more) {
            int kn = (it + 1) << 4;
#pragma unroll
            for (int p = 0; p < 2; p++) {
                int gr = rowBase + arow + p * 64;
                stA[p] = (gr < M) ? *(const float4*)&A[(size_t)gr * K + kn + acol]
                                  : make_float4(0.f, 0.f, 0.f, 0.f);
                int gc = colBase + bcol;
                stB[p] = (gc < N) ? *(const float4*)&B[(size_t)(kn + brow + p * 8) * N + gc]
                                  : make_float4(0.f, 0.f, 0.f, 0.f);
            }
        }

        // MMA phase on buffer `cur` (k-order within tile: kk = 0, 8)
#pragma unroll
        for (int kk = 0; kk < 16; kk += 8) {
            const int kc = kk + (lane & 3);
            uint32_t af[4][4];
#pragma unroll
            for (int mt = 0; mt < 4; mt++) {
                int r0 = wm + mt * 16 + (lane >> 2);
                af[mt][0] = As[cur][r0][kc];
                af[mt][1] = As[cur][r0 + 8][kc];
                af[mt][2] = As[cur][r0][kc + 4];
                af[mt][3] = As[cur][r0 + 8][kc + 4];
            }
            uint32_t bf[4][2];
#pragma unroll
            for (int nt = 0; nt < 4; nt++) {
                int c = wn + nt * 8 + (lane >> 2);
                bf[nt][0] = Bs[cur][kc][c];
                bf[nt][1] = Bs[cur][kc + 4][c];
            }
#pragma unroll
            for (int mt = 0; mt < 4; mt++)
#pragma unroll
                for (int nt = 0; nt < 4; nt++) {
                    asm volatile(
                        "mma.sync.aligned.m16n8k8.row.col.f32.tf32.tf32.f32 "
                        "{%0,%1,%2,%3}, {%4,%5,%6,%7}, {%8,%9}, {%0,%1,%2,%3};\n"
                        : "+f"(acc[mt][nt][0]), "+f"(acc[mt][nt][1]),
                          "+f"(acc[mt][nt][2]), "+f"(acc[mt][nt][3])
                        : "r"(af[mt][0]), "r"(af[mt][1]),
                          "r"(af[mt][2]), "r"(af[mt][3]),
                          "r"(bf[nt][0]), "r"(bf[nt][1]));
                }
        }

        // Commit staged tile it+1 to buffer `nxt`
        if (more) {
#pragma unroll
            for (int p = 0; p < 2; p++) {
                uint4 pa;
                pa.x = f2tf32(stA[p].x); pa.y = f2tf32(stA[p].y);
                pa.z = f2tf32(stA[p].z); pa.w = f2tf32(stA[p].w);
                *(uint4*)&As[nxt][arow + p * 64][acol] = pa;
                uint4 pb;
                pb.x = f2tf32(stB[p].x); pb.y = f2tf32(stB[p].y);
                pb.z = f2tf32(stB[p].z); pb.w = f2tf32(stB[p].w);
                *(uint4*)&Bs[nxt][brow + p * 8][bcol] = pb;
            }
        }
        __syncthreads();
    }

    // Epilogue: bias + store (guarded)
#pragma unroll
    for (int mt = 0; mt < 4; mt++) {
        int row0 = rowBase + wm + mt * 16 + (lane >> 2);
        int row1 = row0 + 8;
#pragma unroll
        for (int nt = 0; nt < 4; nt++) {
            int col = colBase + wn + nt * 8 + (lane & 3) * 2;
            if (col < N) {
                float b0 = bias[col];
                float b1 = bias[col + 1];
                if (row0 < M) {
                    C[(size_t)row0 * N + col]     = acc[mt][nt][0] + b0;
                    C[(size_t)row0 * N + col + 1] = acc[mt][nt][1] + b1;
                }
                if (row1 < M) {
                    C[(size_t)row1 * N + col]     = acc[mt][nt][2] + b0;
                    C[(size_t)row1 * N + col + 1] = acc[mt][nt][3] + b1;
                }
            }
        }
    }
}

// ---------------------------------------------------------------------------
// Fused softmax + sampling-location + deformable sampling/aggregation.
// One warp per (n,q,h). Unchanged from round 12 (34.3 us measured).
// ---------------------------------------------------------------------------
__global__ __launch_bounds__(256) void sample_kernel(const float* __restrict__ refp)
{
    const int warpInBlock = threadIdx.x >> 5;
    const int lane = threadIdx.x & 31;
    const int wg = blockIdx.x * 8 + warpInBlock;   // 0 .. 38399
    const int h  = wg & 7;
    const int fq = wg >> 3;                        // flat (n*300+q)
    const int n  = fq / LQ;

    // --- softmax over 12 logits ---
    float av = (lane < 12) ? g_attn[fq * TPX + h * 12 + lane] : -3.4e38f;
    float m = av;
#pragma unroll
    for (int o = 16; o > 0; o >>= 1)
        m = fmaxf(m, __shfl_xor_sync(0xffffffffu, m, o));
    float e = (lane < 12) ? __expf(av - m) : 0.f;
    float ssum = e;
#pragma unroll
    for (int o = 16; o > 0; o >>= 1)
        ssum += __shfl_xor_sync(0xffffffffu, ssum, o);
    float aw_l = e * (1.f / ssum);

    // --- sampling location for this lane's point ---
    float gx_l = 0.f, gy_l = 0.f;
    if (lane < 12) {
        int l = lane >> 2;
        float4 rp = *(const float4*)&refp[(fq * NL + l) * 4];
        float ox = g_off[fq * 192 + h * 24 + lane * 2 + 0];
        float oy = g_off[fq * 192 + h * 24 + lane * 2 + 1];
        float lx = rp.x + ox * 0.125f * rp.z;
        float ly = rp.y + oy * 0.125f * rp.w;
        gx_l = lx * (float)c_w[l] - 0.5f;
        gy_l = ly * (float)c_h[l] - 0.5f;
    }

    // --- bilinear sampling: 32 lanes = 32 head channels ---
    const int vb = n * (LV * CC) + h * HD + lane;   // fits int32

    float acc = 0.f;
#pragma unroll
    for (int r = 0; r < 12; r++) {
        float gx = __shfl_sync(0xffffffffu, gx_l, r);
        float gy = __shfl_sync(0xffffffffu, gy_l, r);
        float aw = __shfl_sync(0xffffffffu, aw_l, r);
        int l = r >> 2;
        int W = c_w[l], Hh = c_h[l];

        float x0f = floorf(gx), y0f = floorf(gy);
        float fx = gx - x0f, fy = gy - y0f;
        int ix = (int)x0f, iy = (int)y0f;

        bool vx0 = (ix >= 0) & (ix < W);
        bool vx1 = (ix + 1 >= 0) & (ix + 1 < W);
        bool vy0 = (iy >= 0) & (iy < Hh);
        bool vy1 = (iy + 1 >= 0) & (iy + 1 < Hh);

        int base0 = vb + (c_start[l] + iy * W) * CC;    // row iy
        int base1 = base0 + W * CC;                     // row iy+1
        int xoff  = ix * CC;

        float v00 = (vx0 & vy0) ? g_v[base0 + xoff]      : 0.f;
        float v01 = (vx1 & vy0) ? g_v[base0 + xoff + CC] : 0.f;
        float v10 = (vx0 & vy1) ? g_v[base1 + xoff]      : 0.f;
        float v11 = (vx1 & vy1) ? g_v[base1 + xoff + CC] : 0.f;

        float w00 = (1.f - fx) * (1.f - fy);
        float w01 = fx * (1.f - fy);
        float w10 = (1.f - fx) * fy;
        float w11 = fx * fy;
        acc += aw * (v00 * w00 + v01 * w01 + v10 * w10 + v11 * w11);
    }
    g_mid[fq * CC + h * HD + lane] = acc;
}

// ---------------------------------------------------------------------------
extern "C" void kernel_launch(void* const* d_in, const int* in_sizes, int n_in,
                              void* d_out, int out_size)
{
    const float* query = (const float*)d_in[0];
    const float* refp  = (const float*)d_in[1];
    const float* value = (const float*)d_in[2];
    const float* Woff  = (const float*)d_in[3];
    const float* boff  = (const float*)d_in[4];
    const float* Wattn = (const float*)d_in[5];
    const float* battn = (const float*)d_in[6];
    const float* Wval  = (const float*)d_in[7];
    const float* bval  = (const float*)d_in[8];
    const float* Wout  = (const float*)d_in[9];
    const float* bout  = (const float*)d_in[10];
    float* out = (float*)d_out;

    float *d_v, *d_off, *d_attn, *d_mid;
    cudaGetSymbolAddress((void**)&d_v,   g_v);
    cudaGetSymbolAddress((void**)&d_off, g_off);
    cudaGetSymbolAddress((void**)&d_attn,g_attn);
    cudaGetSymbolAddress((void**)&d_mid, g_mid);

    // 1) v = value @ W_val + b_val  (M=134400, N=256, K=256)
    gemm_tf32<<<dim3(2, (NB * LV) / 128), 256>>>(value, Wval, bval, d_v,
                                                 NB * LV, CC, CC);
    // 2) off = query @ W_off + b_off  (M=4800, N=192)
    gemm_tf32<<<dim3(2, (NQ + 127) / 128), 256>>>(query, Woff, boff, d_off,
                                                  NQ, 192, CC);
    // 3) attn = query @ W_attn + b_attn  (M=4800, N=96)
    gemm_tf32<<<dim3(1, (NQ + 127) / 128), 256>>>(query, Wattn, battn, d_attn,
                                                  NQ, TPX, CC);
    // 4) fused softmax + locations + deformable sampling/aggregation
    sample_kernel<<<(NQ * NH) / 8, 256>>>(refp);
    // 5) out = mid @ W_out + b_out  (M=4800, N=256)
    gemm_tf32<<<dim3(2, (NQ + 127) / 128), 256>>>(d_mid, Wout, bout, out,
                                                  NQ, CC, CC);
}

// round 15
// speedup vs baseline: 1.1289x; 1.1289x over previous
#include <cuda_runtime.h>
#include <cuda_bf16.h>
#include <math.h>
#include <stdint.h>

// Problem constants
#define NB 16          // batch
#define LQ 300         // queries
#define CC 256         // channels
#define NH 8           // heads
#define HD 32          // head dim
#define NL 3           // levels
#define NP 4           // points
#define LV 8400        // total spatial positions
#define TPX 96         // H*L*P
#define NQ (NB * LQ)   // 4800 flat queries

// Scratch (device globals; no runtime allocation allowed)
__device__ float  g_v[NB * LV * CC];          // value @ W_val + b_val   (137.6 MB)
__device__ float  g_off[NQ * 192];            // offset GEMM out         (3.7 MB)
__device__ float  g_attn[NQ * TPX];           // attn GEMM out (pre-softmax)
__device__ float  g_mid[NQ * CC];             // per-head aggregated     (4.9 MB)

__constant__ int c_start[NL] = {0, 6400, 8000};
__constant__ int c_w[NL]     = {80, 40, 20};
__constant__ int c_h[NL]     = {80, 40, 20};

// ---------------------------------------------------------------------------
// TF32 tensor-core GEMM: C = A(MxK) @ B(KxN) + bias
// Round-8 shape (best measured): BM=128, BN=128, BK=32, single-buffered,
// register-staged prefetch, 8 warps (2M x 4N), warp tile 64x32.
// NEW: __launch_bounds__(256, 2) forces <=128 regs -> 2 CTAs/SM so the
// two resident CTAs overlap each other's load/commit/barrier phases.
// A smem pitch 36 -> bank=(4r+k)%32 bijective over 8x4 frag footprint.
// K % 32 == 0; M, N guarded.
// ---------------------------------------------------------------------------
__device__ __forceinline__ uint32_t f2tf32(float f) {
    uint32_t r;
    asm("cvt.rna.tf32.f32 %0, %1;" : "=r"(r) : "f"(f));
    return r;
}

__global__ __launch_bounds__(256, 2) void gemm_tf32(
    const float* __restrict__ A, const float* __restrict__ B,
    const float* __restrict__ bias, float* __restrict__ C,
    int M, int N, int K)
{
    __shared__ uint32_t As[128][36];   // [m][k]  18.4 KB
    __shared__ uint32_t Bs[32][132];   // [k][n]  16.9 KB

    const int tid  = threadIdx.x;
    const int lane = tid & 31;
    const int warp = tid >> 5;
    const int wm = (warp >> 2) * 64;   // warp M offset (0 or 64)
    const int wn = (warp & 3) * 32;    // warp N offset (0,32,64,96)
    const int rowBase = blockIdx.y * 128;
    const int colBase = blockIdx.x * 128;

    float acc[4][4][4];
#pragma unroll
    for (int i = 0; i < 4; i++)
#pragma unroll
        for (int j = 0; j < 4; j++)
#pragma unroll
            for (int r = 0; r < 4; r++) acc[i][j][r] = 0.f;

    const int arow  = tid >> 3;         // 0..31, A: 4 passes of 32 rows
    const int acol  = (tid & 7) * 4;    // 0,4,...,28
    const int brow8 = tid >> 5;         // 0..7,  B: 4 passes of 8 rows
    const int bcol  = (tid & 31) * 4;   // 0..124

    float4 stA[4], stB[4];

    // Prologue: stage k-tile 0
#pragma unroll
    for (int p = 0; p < 4; p++) {
        int gr = rowBase + arow + p * 32;
        stA[p] = (gr < M) ? *(const float4*)&A[(size_t)gr * K + acol]
                          : make_float4(0.f, 0.f, 0.f, 0.f);
    }
#pragma unroll
    for (int p = 0; p < 4; p++) {
        int gc = colBase + bcol;
        stB[p] = (gc < N) ? *(const float4*)&B[(size_t)(brow8 + p * 8) * N + gc]
                          : make_float4(0.f, 0.f, 0.f, 0.f);
    }

    for (int k0 = 0; k0 < K; k0 += 32) {
        // Commit staged tile to smem (rna conversion once per element)
#pragma unroll
        for (int p = 0; p < 4; p++) {
            uint4 pk;
            pk.x = f2tf32(stA[p].x);
            pk.y = f2tf32(stA[p].y);
            pk.z = f2tf32(stA[p].z);
            pk.w = f2tf32(stA[p].w);
            *(uint4*)&As[arow + p * 32][acol] = pk;
        }
#pragma unroll
        for (int p = 0; p < 4; p++) {
            uint4 pk;
            pk.x = f2tf32(stB[p].x);
            pk.y = f2tf32(stB[p].y);
            pk.z = f2tf32(stB[p].z);
            pk.w = f2tf32(stB[p].w);
            *(uint4*)&Bs[brow8 + p * 8][bcol] = pk;
        }
        __syncthreads();

        // Prefetch next k-tile into registers (overlaps with MMA phase)
        int kn = k0 + 32;
        if (kn < K) {
#pragma unroll
            for (int p = 0; p < 4; p++) {
                int gr = rowBase + arow + p * 32;
                stA[p] = (gr < M) ? *(const float4*)&A[(size_t)gr * K + kn + acol]
                                  : make_float4(0.f, 0.f, 0.f, 0.f);
            }
#pragma unroll
            for (int p = 0; p < 4; p++) {
                int gc = colBase + bcol;
                stB[p] = (gc < N) ? *(const float4*)&B[(size_t)(kn + brow8 + p * 8) * N + gc]
                                  : make_float4(0.f, 0.f, 0.f, 0.f);
            }
        }

        // MMA phase: 64 MMAs per warp per k-tile
#pragma unroll
        for (int kk = 0; kk < 32; kk += 8) {
            const int kc = kk + (lane & 3);
            uint32_t af[4][4];
#pragma unroll
            for (int mt = 0; mt < 4; mt++) {
                int r0 = wm + mt * 16 + (lane >> 2);
                af[mt][0] = As[r0][kc];
                af[mt][1] = As[r0 + 8][kc];
                af[mt][2] = As[r0][kc + 4];
                af[mt][3] = As[r0 + 8][kc + 4];
            }
            uint32_t bf[4][2];
#pragma unroll
            for (int nt = 0; nt < 4; nt++) {
                int c = wn + nt * 8 + (lane >> 2);
                bf[nt][0] = Bs[kc][c];
                bf[nt][1] = Bs[kc + 4][c];
            }
#pragma unroll
            for (int mt = 0; mt < 4; mt++)
#pragma unroll
                for (int nt = 0; nt < 4; nt++) {
                    asm volatile(
                        "mma.sync.aligned.m16n8k8.row.col.f32.tf32.tf32.f32 "
                        "{%0,%1,%2,%3}, {%4,%5,%6,%7}, {%8,%9}, {%0,%1,%2,%3};\n"
                        : "+f"(acc[mt][nt][0]), "+f"(acc[mt][nt][1]),
                          "+f"(acc[mt][nt][2]), "+f"(acc[mt][nt][3])
                        : "r"(af[mt][0]), "r"(af[mt][1]),
                          "r"(af[mt][2]), "r"(af[mt][3]),
                          "r"(bf[nt][0]), "r"(bf[nt][1]));
                }
        }
        __syncthreads();
    }

    // Epilogue: bias + store (guarded)
#pragma unroll
    for (int mt = 0; mt < 4; mt++) {
        int row0 = rowBase + wm + mt * 16 + (lane >> 2);
        int row1 = row0 + 8;
#pragma unroll
        for (int nt = 0; nt < 4; nt++) {
            int col = colBase + wn + nt * 8 + (lane & 3) * 2;
            if (col < N) {
                float b0 = bias[col];
                float b1 = bias[col + 1];
                if (row0 < M) {
                    C[(size_t)row0 * N + col]     = acc[mt][nt][0] + b0;
                    C[(size_t)row0 * N + col + 1] = acc[mt][nt][1] + b1;
                }
                if (row1 < M) {
                    C[(size_t)row1 * N + col]     = acc[mt][nt][2] + b0;
                    C[(size_t)row1 * N + col + 1] = acc[mt][nt][3] + b1;
                }
            }
        }
    }
}

// ---------------------------------------------------------------------------
// Fused softmax + sampling-location + deformable sampling/aggregation.
// One warp per (n,q,h). Round-12 version (34.3 us measured).
// ---------------------------------------------------------------------------
__global__ __launch_bounds__(256) void sample_kernel(const float* __restrict__ refp)
{
    const int warpInBlock = threadIdx.x >> 5;
    const int lane = threadIdx.x & 31;
    const int wg = blockIdx.x * 8 + warpInBlock;   // 0 .. 38399
    const int h  = wg & 7;
    const int fq = wg >> 3;                        // flat (n*300+q)
    const int n  = fq / LQ;

    // --- softmax over 12 logits ---
    float av = (lane < 12) ? g_attn[fq * TPX + h * 12 + lane] : -3.4e38f;
    float m = av;
#pragma unroll
    for (int o = 16; o > 0; o >>= 1)
        m = fmaxf(m, __shfl_xor_sync(0xffffffffu, m, o));
    float e = (lane < 12) ? __expf(av - m) : 0.f;
    float ssum = e;
#pragma unroll
    for (int o = 16; o > 0; o >>= 1)
        ssum += __shfl_xor_sync(0xffffffffu, ssum, o);
    float aw_l = e * (1.f / ssum);

    // --- sampling location for this lane's point ---
    float gx_l = 0.f, gy_l = 0.f;
    if (lane < 12) {
        int l = lane >> 2;
        float4 rp = *(const float4*)&refp[(fq * NL + l) * 4];
        float ox = g_off[fq * 192 + h * 24 + lane * 2 + 0];
        float oy = g_off[fq * 192 + h * 24 + lane * 2 + 1];
        float lx = rp.x + ox * 0.125f * rp.z;
        float ly = rp.y + oy * 0.125f * rp.w;
        gx_l = lx * (float)c_w[l] - 0.5f;
        gy_l = ly * (float)c_h[l] - 0.5f;
    }

    // --- bilinear sampling: 32 lanes = 32 head channels ---
    const int vb = n * (LV * CC) + h * HD + lane;   // fits int32

    float acc = 0.f;
#pragma unroll
    for (int r = 0; r < 12; r++) {
        float gx = __shfl_sync(0xffffffffu, gx_l, r);
        float gy = __shfl_sync(0xffffffffu, gy_l, r);
        float aw = __shfl_sync(0xffffffffu, aw_l, r);
        int l = r >> 2;
        int W = c_w[l], Hh = c_h[l];

        float x0f = floorf(gx), y0f = floorf(gy);
        float fx = gx - x0f, fy = gy - y0f;
        int ix = (int)x0f, iy = (int)y0f;

        bool vx0 = (ix >= 0) & (ix < W);
        bool vx1 = (ix + 1 >= 0) & (ix + 1 < W);
        bool vy0 = (iy >= 0) & (iy < Hh);
        bool vy1 = (iy + 1 >= 0) & (iy + 1 < Hh);

        int base0 = vb + (c_start[l] + iy * W) * CC;    // row iy
        int base1 = base0 + W * CC;                     // row iy+1
        int xoff  = ix * CC;

        float v00 = (vx0 & vy0) ? g_v[base0 + xoff]      : 0.f;
        float v01 = (vx1 & vy0) ? g_v[base0 + xoff + CC] : 0.f;
        float v10 = (vx0 & vy1) ? g_v[base1 + xoff]      : 0.f;
        float v11 = (vx1 & vy1) ? g_v[base1 + xoff + CC] : 0.f;

        float w00 = (1.f - fx) * (1.f - fy);
        float w01 = fx * (1.f - fy);
        float w10 = (1.f - fx) * fy;
        float w11 = fx * fy;
        acc += aw * (v00 * w00 + v01 * w01 + v10 * w10 + v11 * w11);
    }
    g_mid[fq * CC + h * HD + lane] = acc;
}

// ---------------------------------------------------------------------------
extern "C" void kernel_launch(void* const* d_in, const int* in_sizes, int n_in,
                              void* d_out, int out_size)
{
    const float* query = (const float*)d_in[0];
    const float* refp  = (const float*)d_in[1];
    const float* value = (const float*)d_in[2];
    const float* Woff  = (const float*)d_in[3];
    const float* boff  = (const float*)d_in[4];
    const float* Wattn = (const float*)d_in[5];
    const float* battn = (const float*)d_in[6];
    const float* Wval  = (const float*)d_in[7];
    const float* bval  = (const float*)d_in[8];
    const float* Wout  = (const float*)d_in[9];
    const float* bout  = (const float*)d_in[10];
    float* out = (float*)d_out;

    float *d_v, *d_off, *d_attn, *d_mid;
    cudaGetSymbolAddress((void**)&d_v,   g_v);
    cudaGetSymbolAddress((void**)&d_off, g_off);
    cudaGetSymbolAddress((void**)&d_attn,g_attn);
    cudaGetSymbolAddress((void**)&d_mid, g_mid);

    // 1) v = value @ W_val + b_val  (M=134400, N=256, K=256)
    gemm_tf32<<<dim3(2, (NB * LV) / 128), 256>>>(value, Wval, bval, d_v,
                                                 NB * LV, CC, CC);
    // 2) off = query @ W_off + b_off  (M=4800, N=192)
    gemm_tf32<<<dim3(2, (NQ + 127) / 128), 256>>>(query, Woff, boff, d_off,
                                                  NQ, 192, CC);
    // 3) attn = query @ W_attn + b_attn  (M=4800, N=96)
    gemm_tf32<<<dim3(1, (NQ + 127) / 128), 256>>>(query, Wattn, battn, d_attn,
                                                  NQ, TPX, CC);
    // 4) fused softmax + locations + deformable sampling/aggregation
    sample_kernel<<<(NQ * NH) / 8, 256>>>(refp);
    // 5) out = mid @ W_out + b_out  (M=4800, N=256)
    gemm_tf32<<<dim3(2, (NQ + 127) / 128), 256>>>(d_mid, Wout, bout, out,
                                                  NQ, CC, CC);
}